// round 13
// baseline (speedup 1.0000x reference)
#include <cuda_runtime.h>
#include <cuda_bf16.h>
#include <cstdint>

// Quantizer: per-group(128) absmax -> PoT scale -> int8 quantize -> dequantize (fused=1).
// Persistent grid-stride variant: 2368 CTAs (148 SMs x 16) x 256 threads; each
// warp loops over warp-units of 2 groups (2 independent front-batched LDG.128
// per lane per iteration), default cache policy both ways. Single wave —
// eliminates ~27 wave transitions + tail raggedness of the one-shot grid.
// HBM-roofline-bound: 512 MB @ ~6.35 TB/s achieved => ~75.5us kernel floor.
// Pitfall (measured): __stcs stores cost ~20% DRAM efficiency — do not use.

static constexpr float Q_MAX = 127.0f;
static constexpr float Q_MIN = -128.0f;

__device__ __forceinline__ float4 qdq4(float4 v, float inv, float scale) {
    float4 o;
    o.x = fminf(fmaxf(rintf(v.x * inv), Q_MIN), Q_MAX) * scale;
    o.y = fminf(fmaxf(rintf(v.y * inv), Q_MIN), Q_MAX) * scale;
    o.z = fminf(fmaxf(rintf(v.z * inv), Q_MIN), Q_MAX) * scale;
    o.w = fminf(fmaxf(rintf(v.w * inv), Q_MIN), Q_MAX) * scale;
    return o;
}

__device__ __forceinline__ float absmax4(float4 v) {
    return fmaxf(fmaxf(fabsf(v.x), fabsf(v.y)), fmaxf(fabsf(v.z), fabsf(v.w)));
}

__device__ __forceinline__ void pot_scale(float m, int s_hi, float& inv, float& scale) {
    // scale0 = absmax/127 ; s = clip(ceil(log2(scale0)), 0, s_hi); scale = 2^s
    float scale0 = m * (1.0f / 127.0f);
    int s = (scale0 > 0.0f) ? (int)ceilf(log2f(scale0)) : 0;  // log2(0)=-inf -> clips to 0
    s = max(0, min(s_hi, s));
    scale = exp2f((float)s);        // exact power of two (fp16-exact)
    inv   = exp2f((float)(-s));     // exact reciprocal
}

__global__ void __launch_bounds__(256)
quantizer_qdq_kernel(const float4* __restrict__ in,
                     float4* __restrict__ out,
                     const int* __restrict__ w_scale_bits_p,
                     unsigned int n_vec4)
{
    const unsigned int warps_per_block = blockDim.x >> 5;
    const unsigned int n_warps = gridDim.x * warps_per_block;     // total warps
    const unsigned int warp0 = blockIdx.x * warps_per_block + (threadIdx.x >> 5);
    const unsigned int lane = threadIdx.x & 31;

    const int s_hi = (1 << (w_scale_bits_p ? __ldg(w_scale_bits_p) : 3)) - 1;

    // Grid-stride over warp-units of 64 float4s (2 groups of 128 floats)
    for (unsigned int wu = warp0; wu * 64u + lane < n_vec4; wu += n_warps) {
        const unsigned int i0 = wu * 64u + lane;
        const unsigned int i1 = i0 + 32u;
        const bool has1 = (i1 < n_vec4);

        // Front-batched independent loads (MLP=2), default cache path
        const float4 v0 = in[i0];
        float4 v1 = make_float4(0.f, 0.f, 0.f, 0.f);
        if (has1) v1 = in[i1];

        // Two independent warp max-reductions, interleaved for ILP
        float m0 = absmax4(v0);
        float m1 = absmax4(v1);
        #pragma unroll
        for (int o = 16; o > 0; o >>= 1) {
            m0 = fmaxf(m0, __shfl_xor_sync(0xFFFFFFFFu, m0, o));
            m1 = fmaxf(m1, __shfl_xor_sync(0xFFFFFFFFu, m1, o));
        }

        float inv0, sc0, inv1, sc1;
        pot_scale(m0, s_hi, inv0, sc0);
        pot_scale(m1, s_hi, inv1, sc1);

        // Default-policy stores (L2 write-coalescing intact)
        out[i0] = qdq4(v0, inv0, sc0);
        if (has1) out[i1] = qdq4(v1, inv1, sc1);
    }
}

extern "C" void kernel_launch(void* const* d_in, const int* in_sizes, int n_in,
                              void* d_out, int out_size)
{
    const float* t = (const float*)d_in[0];
    const int* w_scale_bits = (n_in >= 3) ? (const int*)d_in[2] : nullptr;

    const unsigned int n = (unsigned int)in_sizes[0];    // 67108864 floats
    const unsigned int n_vec4 = n >> 2;                  // 16777216 float4s

    const int threads = 256;                             // 8 warps/block
    // Persistent single-wave grid: 148 SMs x 16 CTAs (occ 8 per SM-pair slot),
    // capped by total work.
    const unsigned int warps_per_block = threads / 32;
    const unsigned int n_warp_units = (n_vec4 + 63u) / 64u;   // 262144 units
    unsigned int blocks = 148u * 16u;                          // 2368
    const unsigned int max_blocks =
        (n_warp_units + warps_per_block - 1u) / warps_per_block;
    if (blocks > max_blocks) blocks = max_blocks;

    quantizer_qdq_kernel<<<blocks, threads>>>(
        (const float4*)t, (float4*)d_out, w_scale_bits, n_vec4);
}